// round 1
// baseline (speedup 1.0000x reference)
#include <cuda_runtime.h>
#include <cstdint>

// Problem shape (fixed by the dataset)
#define BB 256
#define TT 199          // MAX_STEP - 1
#define QQ 1000
#define NROW (BB * TT)                 // 50,944
#define NEL  ((size_t)NROW * QQ)       // 50,944,000

// Per-batch accumulators (scratch: __device__ globals, no allocation)
__device__ double g_bce[BB];
__device__ int    g_cnt[BB];

__global__ void init_acc_kernel() {
    int i = threadIdx.x;
    if (i < BB) { g_bce[i] = 0.0; g_cnt[i] = 0; }
}

// One block per (b, t) row of 1000 elements.
__global__ __launch_bounds__(256) void row_kernel(
    const float* __restrict__ pred,    // (B, T, Q)
    const float* __restrict__ batch,   // (B, T+1, Q)
    float* __restrict__ out)
{
    const int t   = blockIdx.x;
    const int b   = blockIdx.y;
    const int tid = threadIdx.x;

    __shared__ float s_gt[QQ];
    __shared__ int   s_flag;
    __shared__ float s_red[8];

    if (tid == 0) s_flag = 0;
    __syncthreads();

    // gt row = batch[b, t+1, :]
    const float* gt_row = batch + ((size_t)b * (TT + 1) + (t + 1)) * QQ;

    int any = 0;
    for (int q = tid; q < QQ; q += 256) {
        float g = gt_row[q];
        s_gt[q] = g;
        any |= (g == 1.0f);
    }
    if (__any_sync(0xFFFFFFFFu, any)) {
        if ((tid & 31) == 0) s_flag = 1;
    }
    __syncthreads();

    const size_t row      = (size_t)b * TT + t;
    float* __restrict__ out_pred = out + 1 + row * QQ;
    float* __restrict__ out_gt   = out + 1 + NEL + row * QQ;

    float lsum = 0.0f;
    const int masked = s_flag;

    if (masked) {
        const float* __restrict__ p_row = pred + row * QQ;
        for (int q = tid; q < QQ; q += 256) {
            float p = p_row[q];
            float g = s_gt[q];
            float lp  = fmaxf(__logf(p), -100.0f);
            float l1p = fmaxf(log1pf(-p), -100.0f);
            lsum += -(g * lp + (1.0f - g) * l1p);
            out_pred[q] = p;
            out_gt[q]   = g;
        }
    } else {
        for (int q = tid; q < QQ; q += 256) {
            out_pred[q] = 0.0f;
            out_gt[q]   = 0.0f;
        }
    }

    // Block reduction of lsum
    #pragma unroll
    for (int off = 16; off > 0; off >>= 1)
        lsum += __shfl_down_sync(0xFFFFFFFFu, lsum, off);
    if ((tid & 31) == 0) s_red[tid >> 5] = lsum;
    __syncthreads();
    if (tid < 32) {
        float v = (tid < 8) ? s_red[tid] : 0.0f;
        #pragma unroll
        for (int off = 4; off > 0; off >>= 1)
            v += __shfl_down_sync(0xFFFFFFFFu, v, off);
        if (tid == 0) {
            if (masked) {
                atomicAdd(&g_bce[b], (double)v);
                atomicAdd(&g_cnt[b], 1);
            }
            // row_mask output (float 0/1), offset 1 + 2*NEL
            out[1 + 2 * NEL + row] = masked ? 1.0f : 0.0f;
        }
    }
}

__global__ void final_kernel(float* __restrict__ out) {
    __shared__ double s[BB];
    int b = threadIdx.x;
    int c = g_cnt[b];
    double denom = (double)c * (double)QQ;
    s[b] = (c > 0) ? (g_bce[b] / denom) : 0.0;
    __syncthreads();
    #pragma unroll
    for (int off = BB / 2; off > 0; off >>= 1) {
        if (b < off) s[b] += s[b + off];
        __syncthreads();
    }
    if (b == 0) out[0] = (float)s[0];
}

extern "C" void kernel_launch(void* const* d_in, const int* in_sizes, int n_in,
                              void* d_out, int out_size) {
    const float* pred  = (const float*)d_in[0];
    const float* batch = (const float*)d_in[1];
    float* out = (float*)d_out;

    init_acc_kernel<<<1, BB>>>();
    dim3 grid(TT, BB);
    row_kernel<<<grid, 256>>>(pred, batch, out);
    final_kernel<<<1, BB>>>(out);
}

// round 2
// speedup vs baseline: 1.8463x; 1.8463x over previous
#include <cuda_runtime.h>
#include <cstdint>

#define BB 256
#define TT 199
#define QQ 1000
#define NROW (BB * TT)               // 50,944
#define NEL  ((size_t)NROW * QQ)     // 50,944,000

// Scratch (__device__ globals, no allocation)
__device__ float  g_rowbce[NROW];
__device__ double g_perb[BB];

// One block per (b, t) row of 1000 elements. tid-stride mapping (coalesced).
__global__ __launch_bounds__(256) void row_kernel(
    const float* __restrict__ pred,    // (B, T, Q)
    const float* __restrict__ batch,   // (B, T+1, Q)
    float* __restrict__ out)
{
    const int t   = blockIdx.x;
    const int b   = blockIdx.y;
    const int tid = threadIdx.x;
    const int lane = tid & 31;
    const int wid  = tid >> 5;

    const size_t row = (size_t)b * TT + t;
    const float* __restrict__ gt_row = batch + ((size_t)b * (TT + 1) + (t + 1)) * QQ;
    const float* __restrict__ p_row  = pred + row * QQ;

    __shared__ int   s_w[8];
    __shared__ float s_red[8];

    // Load everything up front, unconditionally (max MLP, no serialization).
    float g[4], p[4];
    #pragma unroll
    for (int k = 0; k < 4; k++) {
        int q = tid + 256 * k;
        bool valid = (k < 3) || (tid < QQ - 768);   // q < 1000
        // Dummy (g=0, p=0) contributes exactly 0 to bce:
        //   g*max(log 0,-100) = 0*(-100) = 0 ; (1-g)*log(1-0) = 0
        g[k] = valid ? gt_row[q] : 0.0f;
        p[k] = valid ? p_row[q]  : 0.0f;
    }

    // Block-wide "any(g == 1)" via ballot + smem OR.
    int anyv = (g[0] == 1.0f) | (g[1] == 1.0f) | (g[2] == 1.0f) | (g[3] == 1.0f);
    unsigned wany = __ballot_sync(0xFFFFFFFFu, anyv);
    if (lane == 0) s_w[wid] = (wany != 0);
    __syncthreads();
    const int masked = s_w[0] | s_w[1] | s_w[2] | s_w[3] |
                       s_w[4] | s_w[5] | s_w[6] | s_w[7];
    const float fm = masked ? 1.0f : 0.0f;

    float* __restrict__ out_pred = out + 1 + row * QQ;
    float* __restrict__ out_gt   = out + 1 + NEL + row * QQ;

    float lsum = 0.0f;   // accumulates +(g*log p + (1-g)*log(1-p)); bce = -lsum
    #pragma unroll
    for (int k = 0; k < 4; k++) {
        int q = tid + 256 * k;
        bool valid = (k < 3) || (tid < QQ - 768);
        float pp = p[k], gg = g[k];
        float lp = fmaxf(__logf(pp),        -100.0f);
        float l1 = fmaxf(__logf(1.0f - pp), -100.0f);
        lsum += gg * lp + (1.0f - gg) * l1;
        if (valid) {
            out_pred[q] = pp * fm;
            out_gt[q]   = gg * fm;
        }
    }

    // Block reduction of lsum.
    #pragma unroll
    for (int off = 16; off > 0; off >>= 1)
        lsum += __shfl_down_sync(0xFFFFFFFFu, lsum, off);
    if (lane == 0) s_red[wid] = lsum;
    __syncthreads();
    if (tid < 32) {
        float v = (tid < 8) ? s_red[tid] : 0.0f;
        #pragma unroll
        for (int off = 4; off > 0; off >>= 1)
            v += __shfl_down_sync(0xFFFFFFFFu, v, off);
        if (tid == 0) {
            g_rowbce[row] = fm * (-v);
            out[1 + 2 * NEL + row] = fm;   // row_mask as float 0/1
        }
    }
}

// Per-batch reduction: block b sums its 199 rows.
__global__ __launch_bounds__(64) void final1_kernel(const float* __restrict__ out)
{
    const int b   = blockIdx.x;
    const int tid = threadIdx.x;
    const int lane = tid & 31;
    const int wid  = tid >> 5;

    __shared__ float s_s[2];
    __shared__ int   s_c[2];

    float sum = 0.0f;
    int   cnt = 0;
    for (int t = tid; t < TT; t += 64) {
        size_t row = (size_t)b * TT + t;
        sum += g_rowbce[row];
        cnt += (int)out[1 + 2 * NEL + row];
    }
    #pragma unroll
    for (int off = 16; off > 0; off >>= 1) {
        sum += __shfl_down_sync(0xFFFFFFFFu, sum, off);
        cnt += __shfl_down_sync(0xFFFFFFFFu, cnt, off);
    }
    if (lane == 0) { s_s[wid] = sum; s_c[wid] = cnt; }
    __syncthreads();
    if (tid == 0) {
        float s = s_s[0] + s_s[1];
        int   c = s_c[0] + s_c[1];
        g_perb[b] = (c > 0) ? ((double)s / ((double)c * (double)QQ)) : 0.0;
    }
}

// Global sum of per-batch values.
__global__ __launch_bounds__(256) void final2_kernel(float* __restrict__ out)
{
    __shared__ double s[BB];
    int b = threadIdx.x;
    s[b] = g_perb[b];
    __syncthreads();
    #pragma unroll
    for (int off = BB / 2; off > 0; off >>= 1) {
        if (b < off) s[b] += s[b + off];
        __syncthreads();
    }
    if (b == 0) out[0] = (float)s[0];
}

extern "C" void kernel_launch(void* const* d_in, const int* in_sizes, int n_in,
                              void* d_out, int out_size) {
    const float* pred  = (const float*)d_in[0];
    const float* batch = (const float*)d_in[1];
    float* out = (float*)d_out;

    dim3 grid(TT, BB);
    row_kernel<<<grid, 256>>>(pred, batch, out);
    final1_kernel<<<BB, 64>>>(out);
    final2_kernel<<<1, BB>>>(out);
}